// round 12
// baseline (speedup 1.0000x reference)
#include <cuda_runtime.h>
#include <cuda_fp16.h>
#include <cstdint>

#define BB      2048
#define NN      64
#define DD      256
#define NSTEPS  4
#define MTILE   128            // batch rows per CTA
#define THREADS 1024           // 32 warps: 8 (M) x 4 (N)
#define XSH     264            // xs_h row stride in halfs (528B)

// SMEM layout (bytes)
#define XSH_BYTES  (MTILE * XSH * 2)      // 67584
#define BIAS_OFF   XSH_BYTES              // 1024 B fp32
#define WBUF_OFF   (BIAS_OFF + 1024)      // 68608
#define SMEM_MAX   (WBUF_OFF + 131072)    // 199680 <= 227KB (1 CTA/SM)

// Scratch (device globals)
// g_wpack[n][kc32][t][lane] (uint4): masked W fp16, m16n8k16 B-frag order.
//   j = t*8 + (lane>>2); i0 = kc32*32 + 2*(lane&3);
//   .x=(i0,i0+1) .y=(+8,+9) [sub0];  .z=(+16,+17) .w=(+24,+25) [sub1]
// Granule stride: 1024 uint4 (32 tiles always); active tiles t < 4*NT contiguous.
__device__ __align__(16) uint4 g_wpack[NN * 8 * 32 * 32];
__device__ float g_b[NN * DD];
__device__ int   g_nact[NN];

// ---------------------------------------------------------------------------
// PTX helpers (plain sm_80+ PTX)
// ---------------------------------------------------------------------------
__device__ __forceinline__ void mma16816(float* d, const uint32_t* a,
                                         uint32_t b0, uint32_t b1) {
    asm volatile(
        "mma.sync.aligned.m16n8k16.row.col.f32.f16.f16.f32 "
        "{%0,%1,%2,%3}, {%4,%5,%6,%7}, {%8,%9}, {%0,%1,%2,%3};"
        : "+f"(d[0]), "+f"(d[1]), "+f"(d[2]), "+f"(d[3])
        : "r"(a[0]), "r"(a[1]), "r"(a[2]), "r"(a[3]), "r"(b0), "r"(b1));
}
__device__ __forceinline__ void ldmatrix4(uint32_t* a, uint32_t addr) {
    asm volatile("ldmatrix.sync.aligned.m8n8.x4.shared.b16 {%0,%1,%2,%3}, [%4];"
                 : "=r"(a[0]), "=r"(a[1]), "=r"(a[2]), "=r"(a[3]) : "r"(addr));
}
__device__ __forceinline__ void cp16(uint32_t s_dst, const void* g_src) {
    asm volatile("cp.async.cg.shared.global [%0], [%1], 16;"
                 :: "r"(s_dst), "l"(g_src) : "memory");
}
__device__ __forceinline__ void cp_commit() {
    asm volatile("cp.async.commit_group;" ::: "memory");
}
__device__ __forceinline__ void cp_wait0() {
    asm volatile("cp.async.wait_group 0;" ::: "memory");
}
__device__ __forceinline__ uint32_t h2u(__half2 h) { return *(uint32_t*)&h; }

// ---------------------------------------------------------------------------
// Prep: premask W -> fp16 uint4 B-fragments; blocks >= 2048 do bias + nact
// ---------------------------------------------------------------------------
__global__ void prep_kernel(const float* __restrict__ w,
                            const float* __restrict__ wm,
                            const float* __restrict__ b,
                            const float* __restrict__ bm) {
    if (blockIdx.x >= 2048) {
        const int n = blockIdx.x - 2048, t = threadIdx.x;
        __shared__ int cnt;
        if (t == 0) cnt = 0;
        __syncthreads();
        float m = bm[n * DD + t];
        g_b[n * DD + t] = b[n * DD + t] * m;
        if (m != 0.f) atomicAdd(&cnt, 1);
        __syncthreads();
        if (t == 0) g_nact[n] = cnt;
        return;
    }
    int q = blockIdx.x * 256 + threadIdx.x;          // [0, 64*8*32*32)
    int lane = q & 31, t = (q >> 5) & 31, kc = (q >> 10) & 7, n = q >> 13;
    int j = t * 8 + (lane >> 2);
    int i0 = kc * 32 + 2 * (lane & 3);
    size_t base = ((size_t)n * DD + j) * DD + i0;
    uint4 r;
    {
        float2 v = *(const float2*)(w + base), m = *(const float2*)(wm + base);
        r.x = h2u(__floats2half2_rn(v.x * m.x, v.y * m.y));
    }
    {
        float2 v = *(const float2*)(w + base + 8), m = *(const float2*)(wm + base + 8);
        r.y = h2u(__floats2half2_rn(v.x * m.x, v.y * m.y));
    }
    {
        float2 v = *(const float2*)(w + base + 16), m = *(const float2*)(wm + base + 16);
        r.z = h2u(__floats2half2_rn(v.x * m.x, v.y * m.y));
    }
    {
        float2 v = *(const float2*)(w + base + 24), m = *(const float2*)(wm + base + 24);
        r.w = h2u(__floats2half2_rn(v.x * m.x, v.y * m.y));
    }
    g_wpack[q] = r;
}

// ---------------------------------------------------------------------------
// Step driver: W fully resident in SMEM for ALL classes; full-CTA barriers.
// Warp (mi = wid&7, ni = wid>>3) exclusively owns xs rows [mi*16, mi*16+16).
// ---------------------------------------------------------------------------
extern __shared__ __align__(16) unsigned char smem_raw[];

template <int NT>
__device__ __forceinline__ void run_steps(__half* xsh, const float* bsm,
                                          const uint4* wsrc, int nt_rt,
                                          int tid, int wid, int lane) {
    const int nt = (NT > 0) ? NT : nt_rt;
    uint4* wbuf = (uint4*)(smem_raw + WBUF_OFF);
    const uint32_t smem_u = (uint32_t)__cvta_generic_to_shared(smem_raw);
    const uint32_t wb_u = smem_u + WBUF_OFF;

    // Load ALL active W once: nt granules x (128*nt contiguous uint4 each)
    {
        const int per_g = 128 * nt;
        for (int v = tid; v < nt * per_g; v += THREADS) {
            int g = v / per_g, within = v - g * per_g;
            cp16(wb_u + v * 16, wsrc + g * 1024 + within);
        }
        cp_commit(); cp_wait0();
    }
    __syncthreads();           // x tile + bias + W all visible

    const int mi = wid & 7, ni = wid >> 3;   // 8 (M) x 4 (N)
    const int row_l = (lane & 15);
    const int koff = (lane >> 4) * 8;
    const uint32_t abase = smem_u + ((mi * 16 + row_l) * XSH + koff) * 2;

    const int rE = mi * 16 + (lane >> 2);
    const int cq = 2 * (lane & 3);
    const int nbase = ni * nt * 8;

    float acc[(NT > 0) ? NT : 8][4];

    for (int step = 0; step < NSTEPS; ++step) {
#pragma unroll
        for (int t = 0; t < ((NT > 0) ? NT : 8); ++t)
#pragma unroll
            for (int q = 0; q < 4; ++q)
                if (NT > 0 || t < nt_rt) acc[t][q] = 0.f;

#pragma unroll
        for (int s = 0; s < ((NT > 0) ? NT : 8); ++s) {
            if (NT == 0 && s >= nt_rt) break;

            // A fragments: 2 ldmatrix.x4 (k16 subs) for this warp's m16 tile
            uint32_t a[2][4];
            const int kbyte = s * 64;
            ldmatrix4(a[0], abase + kbyte);
            ldmatrix4(a[1], abase + kbyte + 32);

            const uint4* bp = wbuf + s * (128 * nt) + ni * nt * 32 + lane;
#pragma unroll
            for (int t = 0; t < ((NT > 0) ? NT : 8); ++t) {
                if (NT == 0 && t >= nt_rt) break;
                uint4 bfr = bp[t * 32];
                mma16816(acc[t], a[0], bfr.x, bfr.y);
                mma16816(acc[t], a[1], bfr.z, bfr.w);
            }
        }

        __syncthreads();   // all A reads done before epilogue writes xs

        // Epilogue: x += relu(acc + b) in fp32, stored back as fp16
#pragma unroll
        for (int t = 0; t < ((NT > 0) ? NT : 8); ++t) {
            if (NT == 0 && t >= nt_rt) break;
            const int c = nbase + t * 8 + cq;
            float2 bv = *(const float2*)&bsm[c];
            {
                __half2* p = (__half2*)&xsh[rE * XSH + c];
                float2 fx = __half22float2(*p);
                fx.x += fmaxf(acc[t][0] + bv.x, 0.f);
                fx.y += fmaxf(acc[t][1] + bv.y, 0.f);
                *p = __floats2half2_rn(fx.x, fx.y);
            }
            {
                __half2* p = (__half2*)&xsh[(rE + 8) * XSH + c];
                float2 fx = __half22float2(*p);
                fx.x += fmaxf(acc[t][2] + bv.x, 0.f);
                fx.y += fmaxf(acc[t][3] + bv.y, 0.f);
                *p = __floats2half2_rn(fx.x, fx.y);
            }
        }

        __syncthreads();   // epilogue visible before next step's reads
    }
}

// Heavy-first rank -> group mapping (class c = n%5 descending; NT=8 first)
__device__ __forceinline__ int rank_to_n(int r) {
    if (r < 12) return 4 + 5 * r;
    if (r < 25) return 3 + 5 * (r - 12);
    if (r < 38) return 2 + 5 * (r - 25);
    if (r < 51) return 1 + 5 * (r - 38);
    return 5 * (r - 51);
}

__global__ __launch_bounds__(THREADS, 1)
void blm_all_kernel(const float* __restrict__ x_in, float* __restrict__ x_out) {
    const int rank = blockIdx.x >> 4;        // 64 groups x 16 batch tiles
    const int n = rank_to_n(rank);
    const int r0 = (blockIdx.x & 15) * MTILE;
    const int nact = g_nact[n];
    const int nk = nact >> 5;

    __half* xsh = (__half*)smem_raw;
    float* bsm = (float*)(smem_raw + BIAS_OFF);
    const int tid = threadIdx.x;
    const int wid = tid >> 5, lane = tid & 31;

    if (tid < DD) bsm[tid] = g_b[n * DD + tid];

    // Load x tile (128 x 256) -> fp16 SMEM
    {
        const float4* xin4 = (const float4*)x_in;
        for (int v = tid; v < MTILE * 64; v += THREADS) {
            int row = v >> 6, c4 = v & 63;
            float4 f = xin4[((size_t)(r0 + row) * NN + n) * 64 + c4];
            uint2 h;
            h.x = h2u(__floats2half2_rn(f.x, f.y));
            h.y = h2u(__floats2half2_rn(f.z, f.w));
            *(uint2*)&xsh[row * XSH + c4 * 4] = h;
        }
    }
    // run_steps begins with __syncthreads() covering xs/bias/W visibility

    const uint4* wsrc = g_wpack + ((size_t)n << 13);
    switch (nk) {
        case 4: run_steps<4>(xsh, bsm, wsrc, nk, tid, wid, lane); break;
        case 5: run_steps<5>(xsh, bsm, wsrc, nk, tid, wid, lane); break;
        case 6: run_steps<6>(xsh, bsm, wsrc, nk, tid, wid, lane); break;
        case 7: run_steps<7>(xsh, bsm, wsrc, nk, tid, wid, lane); break;
        case 8: run_steps<8>(xsh, bsm, wsrc, nk, tid, wid, lane); break;
        default: run_steps<0>(xsh, bsm, wsrc, nk, tid, wid, lane); break;
    }

    __syncthreads();   // all warps finished before cross-row store

    // Store: active cols from fp16 xs; inactive cols exact fp32 pass-through
    {
        const float4* xin4 = (const float4*)x_in;
        float4* xo = (float4*)x_out;
        for (int v = tid; v < MTILE * 64; v += THREADS) {
            int row = v >> 6, c4 = v & 63;
            size_t gi = ((size_t)(r0 + row) * NN + n) * 64 + c4;
            float4 f;
            if (c4 * 4 < nact) {
                uint2 h = *(const uint2*)&xsh[row * XSH + c4 * 4];
                float2 lo = __half22float2(*(__half2*)&h.x);
                float2 hi = __half22float2(*(__half2*)&h.y);
                f.x = lo.x; f.y = lo.y; f.z = hi.x; f.w = hi.y;
            } else {
                f = xin4[gi];
            }
            xo[gi] = f;
        }
    }
}

// ---------------------------------------------------------------------------
// Launch
// ---------------------------------------------------------------------------
extern "C" void kernel_launch(void* const* d_in, const int* in_sizes, int n_in,
                              void* d_out, int out_size) {
    const float* x  = (const float*)d_in[0];
    const float* w  = (const float*)d_in[1];
    const float* b  = (const float*)d_in[2];
    const float* wm = (const float*)d_in[3];
    const float* bm = (const float*)d_in[4];
    float* out = (float*)d_out;

    cudaFuncSetAttribute(blm_all_kernel,
                         cudaFuncAttributeMaxDynamicSharedMemorySize, SMEM_MAX);

    prep_kernel<<<2048 + 64, 256>>>(w, wm, b, bm);
    blm_all_kernel<<<NN * (BB / MTILE), THREADS, SMEM_MAX>>>(x, out);
}